// round 5
// baseline (speedup 1.0000x reference)
#include <cuda_runtime.h>
#include <cuda_bf16.h>
#include <math_constants.h>

// GAT layer, N=4096, F=128, H=8, D=8 (HD=64)
// Inputs: X[4096,128], A[4096,4096], W[128,64], att_self[64], att_neigh[64], bias[64]
// Output: float [4096, 64]

#define N_NODES 4096
#define F_IN    128
#define HD      64
#define H_NUM   8
#define MAXN    512      // safety cap on neighbors/row (E[n]=41, sigma=6.4)

__device__ float g_feats[N_NODES * HD];
__device__ float g_as[N_NODES * H_NUM];
__device__ float g_an[N_NODES * H_NUM];
__device__ int   g_nz[N_NODES * MAXN];
__device__ int   g_cnt[N_NODES];

// ---------------------------------------------------------------------------
// Kernel A: fused scan + projection.
//  blocks [0, 4096): pure streaming scan of one A row -> compacted nz list.
//  blocks [4096, 4096+256): projection of 16 rows (X@W + per-head scores).
// Union smem keeps the scan branch at 16.5 KB so occupancy stays warp-capped.
// ---------------------------------------------------------------------------
__global__ __launch_bounds__(256) void scan_proj_kernel(
    const float* __restrict__ A, const float* __restrict__ X,
    const float* __restrict__ W,
    const float* __restrict__ att_s, const float* __restrict__ att_n)
{
    __shared__ __align__(16) char smraw[N_NODES * sizeof(int) + 16];
    const int t = threadIdx.x;

    if (blockIdx.x < N_NODES) {
        // ================= scan branch =================
        int* nz = (int*)smraw;
        __shared__ int cnt;
        if (t == 0) cnt = 0;
        __syncthreads();

        const int i = blockIdx.x;
        const float4* Arow = (const float4*)(A + (size_t)i * N_NODES);
        float4 v[4];
#pragma unroll
        for (int q = 0; q < 4; q++) v[q] = Arow[t + 256 * q];
#pragma unroll
        for (int q = 0; q < 4; q++) {
            int j = (t + 256 * q) * 4;
            if (v[q].x != 0.f) nz[atomicAdd(&cnt, 1)] = j;
            if (v[q].y != 0.f) nz[atomicAdd(&cnt, 1)] = j + 1;
            if (v[q].z != 0.f) nz[atomicAdd(&cnt, 1)] = j + 2;
            if (v[q].w != 0.f) nz[atomicAdd(&cnt, 1)] = j + 3;
        }
        __syncthreads();
        const int n = min(cnt, MAXN);
        for (int k = t; k < n; k += 256) g_nz[i * MAXN + k] = nz[k];
        if (t == 0) g_cnt[i] = n;
    } else {
        // ================= projection branch =================
        float* Xs = (float*)smraw;                 // 16 x 128 floats = 8 KB
        const int rowbase = (blockIdx.x - N_NODES) * 16;

        for (int idx = t; idx < 16 * F_IN / 4; idx += 256)
            ((float4*)Xs)[idx] = ((const float4*)(X + (size_t)rowbase * F_IN))[idx];
        __syncthreads();

        const int c4 = (t & 15) * 4;   // column base (within one head)
        const int rl = t >> 4;         // local row 0..15
        const int r  = rowbase + rl;

        float4 as4 = *(const float4*)&att_s[c4];
        float4 an4 = *(const float4*)&att_n[c4];
        const float4* W4 = (const float4*)W;

        float a0 = 0.f, a1 = 0.f, a2 = 0.f, a3 = 0.f;
#pragma unroll 8
        for (int f = 0; f < F_IN; f++) {
            float4 w = __ldg(&W4[f * (HD / 4) + (c4 >> 2)]);   // W stays L1/L2 hot
            float  x = Xs[rl * F_IN + f];
            a0 = fmaf(x, w.x, a0); a1 = fmaf(x, w.y, a1);
            a2 = fmaf(x, w.z, a2); a3 = fmaf(x, w.w, a3);
        }
        *(float4*)&g_feats[r * HD + c4] = make_float4(a0, a1, a2, a3);

        float asum = a0 * as4.x + a1 * as4.y + a2 * as4.z + a3 * as4.w;
        float ansm = a0 * an4.x + a1 * an4.y + a2 * an4.z + a3 * an4.w;
        asum += __shfl_xor_sync(0xffffffffu, asum, 1);   // partner t^1: same head
        ansm += __shfl_xor_sync(0xffffffffu, ansm, 1);
        if ((t & 1) == 0) {
            int h = (t & 15) >> 1;
            g_as[r * H_NUM + h] = asum;
            g_an[r * H_NUM + h] = ansm;
        }
    }
}

// ---------------------------------------------------------------------------
// Kernel B: softmax + aggregation, one block (256 thr) per row.
//  - load nz list (global -> smem)
//  - warp h: online softmax stats for head h, caching leaky logits in smem
//  - one exp per (k,h): convert cached logits to weights
//  - pure-FMA aggregation (4 k-groups), smem reduce, epilogue
// Masked entries contribute exactly 0 in the reference (fp32 exp underflow),
// so the sparse sum is exact.
// ---------------------------------------------------------------------------
__global__ __launch_bounds__(256) void agg_kernel(
    const float* __restrict__ bias, float* __restrict__ out)
{
    __shared__ int   nz_s[MAXN];
    __shared__ float lsm[MAXN * H_NUM];      // logits, then weights (16 KB)
    __shared__ float Msh[H_NUM], Ssh[H_NUM];
    __shared__ float accbuf[256];

    const int i = blockIdx.x;
    const int t = threadIdx.x;
    const int n = g_cnt[i];

    for (int k = t; k < n; k += 256) nz_s[k] = g_nz[i * MAXN + k];
    __syncthreads();

    // ---- per-head softmax stats (warp h owns head h), cache logits ----
    {
        const int h = t >> 5, lane = t & 31;
        const float asi = g_as[i * H_NUM + h];
        float m = -1e30f, s = 0.f;
        for (int k = lane; k < n; k += 32) {
            int j = nz_s[k];
            float l = asi + g_an[j * H_NUM + h];
            l = l > 0.f ? l : 0.2f * l;                  // leaky_relu(0.2)
            lsm[k * H_NUM + h] = l;
            float mn = fmaxf(m, l);
            s = s * __expf(m - mn) + __expf(l - mn);
            m = mn;
        }
#pragma unroll
        for (int o = 16; o > 0; o >>= 1) {
            float m2 = __shfl_xor_sync(0xffffffffu, m, o);
            float s2 = __shfl_xor_sync(0xffffffffu, s, o);
            float mn = fmaxf(m, m2);
            s = s * __expf(m - mn) + s2 * __expf(m2 - mn);
            m = mn;
        }
        if (lane == 0) { Msh[h] = m; Ssh[h] = s; }
    }
    __syncthreads();

    // ---- logits -> weights (one exp per (k,h)) ----
    for (int idx = t; idx < n * H_NUM; idx += 256)
        lsm[idx] = __expf(lsm[idx] - Msh[idx & 7]);
    __syncthreads();

    // ---- aggregation: pure FMA over L2-resident feats ----
    const int o   = t & 63;          // output element (h*8+d)
    const int grp = t >> 6;          // 0..3 k-strided groups
    const int h   = o >> 3;

    float acc = 0.f;
#pragma unroll 4
    for (int k = grp; k < n; k += 4)
        acc = fmaf(lsm[k * H_NUM + h], g_feats[nz_s[k] * HD + o], acc);
    accbuf[t] = acc;
    __syncthreads();

    if (t < HD) {
        float a = accbuf[t] + accbuf[t + 64] + accbuf[t + 128] + accbuf[t + 192];
        float r = a / Ssh[t >> 3] + bias[t];
        out[(size_t)i * HD + t] = fmaxf(r, 0.f);
    }
}

// ---------------------------------------------------------------------------
extern "C" void kernel_launch(void* const* d_in, const int* in_sizes, int n_in,
                              void* d_out, int out_size)
{
    const float* X     = (const float*)d_in[0];
    const float* A     = (const float*)d_in[1];
    const float* W     = (const float*)d_in[2];
    const float* att_s = (const float*)d_in[3];
    const float* att_n = (const float*)d_in[4];
    const float* bias  = (const float*)d_in[5];
    float* out = (float*)d_out;

    scan_proj_kernel<<<N_NODES + N_NODES / 16, 256>>>(A, X, W, att_s, att_n);
    agg_kernel<<<N_NODES, 256>>>(bias, out);
}